// round 2
// baseline (speedup 1.0000x reference)
#include <cuda_runtime.h>

// expm(A - A^T) for N=2048 fp32 via scaling-and-squaring + Taylor/Horner.
//   S = (A - A^T) / 2^SEXP
//   M = I + S/D                       (elementwise)
//   for k = D-1 .. 1:  M = I + (S/k) * M   (GEMM + identity epilogue)
//   repeat SEXP times: M = M * M           (GEMM)
// Truncation error ~ (||S||/2^SEXP)^(D+1)/(D+1)! ~ 4e-16 for ||S||~1.3.

#define MATN 2048
constexpr int SEXP = 4;   // number of squarings
constexpr int DEG  = 8;   // Taylor degree

// Scratch (device globals — no allocation allowed in kernel_launch)
__device__ float g_S[MATN * MATN];
__device__ float g_M[MATN * MATN];
__device__ float g_T[MATN * MATN];

// ---------------------------------------------------------------------------
// S = (A - A^T) * scale, tiled transpose for coalescing
// ---------------------------------------------------------------------------
__global__ void skew_kernel(const float* __restrict__ A, float* __restrict__ S,
                            float scale) {
    __shared__ float tileT[32][33];  // holds A^T block, padded
    int bx = blockIdx.x * 32;
    int by = blockIdx.y * 32;
    int tx = threadIdx.x;
    int ty = threadIdx.y;

    // Load the transposed-source block A[bx.., by..] coalesced
    #pragma unroll
    for (int r = 0; r < 32; r += 8) {
        tileT[ty + r][tx] = A[(bx + ty + r) * MATN + (by + tx)];
    }
    __syncthreads();

    // S[by+i][bx+j] = (A[by+i][bx+j] - A[bx+j][by+i]) * scale
    #pragma unroll
    for (int r = 0; r < 32; r += 8) {
        int row = by + ty + r;
        int col = bx + tx;
        float a  = A[row * MATN + col];
        float at = tileT[tx][ty + r];
        S[row * MATN + col] = (a - at) * scale;
    }
}

// ---------------------------------------------------------------------------
// M = S * alpha + I
// ---------------------------------------------------------------------------
__global__ void init_horner_kernel(const float* __restrict__ S,
                                   float* __restrict__ M, float alpha) {
    int idx = blockIdx.x * blockDim.x + threadIdx.x;
    int row = idx / MATN;
    int col = idx - row * MATN;
    float v = S[idx] * alpha;
    if (row == col) v += 1.0f;
    M[idx] = v;
}

// ---------------------------------------------------------------------------
// C = alpha * A*B (+ I if ADD_I).  128x128 tile, BK=8, 256 threads, 8x8/thread
// ---------------------------------------------------------------------------
template <bool ADD_I>
__global__ __launch_bounds__(256, 2)
void sgemm128(const float* __restrict__ A, const float* __restrict__ B,
              float* __restrict__ C, float alpha) {
    __shared__ float As[8][128];   // A tile, transposed (k-major)
    __shared__ float Bs[8][128];

    const int tid  = threadIdx.x;
    const int brow = blockIdx.y * 128;
    const int bcol = blockIdx.x * 128;

    // A-tile load mapping: 128x8 floats, float4 per thread
    const int arow  = tid >> 1;          // 0..127
    const int acol4 = (tid & 1) << 2;    // 0 or 4
    // B-tile load mapping: 8x128 floats, float4 per thread
    const int brow8 = tid >> 5;          // 0..7
    const int bcol4 = (tid & 31) << 2;   // 0..124

    const int ty = tid >> 4;             // 0..15 (row group)
    const int tx = tid & 15;             // 0..15 (col group)

    float acc[8][8];
    #pragma unroll
    for (int i = 0; i < 8; i++)
        #pragma unroll
        for (int j = 0; j < 8; j++) acc[i][j] = 0.0f;

    const float* Aptr = A + (brow + arow) * MATN + acol4;
    const float* Bptr = B + brow8 * MATN + bcol + bcol4;

    for (int k0 = 0; k0 < MATN; k0 += 8) {
        float4 a4 = *reinterpret_cast<const float4*>(Aptr + k0);
        float4 b4 = *reinterpret_cast<const float4*>(Bptr + (long)k0 * MATN);
        As[acol4 + 0][arow] = a4.x;
        As[acol4 + 1][arow] = a4.y;
        As[acol4 + 2][arow] = a4.z;
        As[acol4 + 3][arow] = a4.w;
        *reinterpret_cast<float4*>(&Bs[brow8][bcol4]) = b4;
        __syncthreads();

        #pragma unroll
        for (int k = 0; k < 8; k++) {
            float ra[8], rb[8];
            #pragma unroll
            for (int i = 0; i < 8; i++) ra[i] = As[k][ty * 8 + i];
            #pragma unroll
            for (int j = 0; j < 8; j++) rb[j] = Bs[k][tx * 8 + j];
            #pragma unroll
            for (int i = 0; i < 8; i++)
                #pragma unroll
                for (int j = 0; j < 8; j++)
                    acc[i][j] = fmaf(ra[i], rb[j], acc[i][j]);
        }
        __syncthreads();
    }

    // Epilogue
    #pragma unroll
    for (int i = 0; i < 8; i++) {
        int row  = brow + ty * 8 + i;
        int col0 = bcol + tx * 8;
        float out[8];
        #pragma unroll
        for (int j = 0; j < 8; j++) {
            float v = acc[i][j] * alpha;
            if (ADD_I && row == (col0 + j)) v += 1.0f;
            out[j] = v;
        }
        float4* cp = reinterpret_cast<float4*>(C + (long)row * MATN + col0);
        cp[0] = make_float4(out[0], out[1], out[2], out[3]);
        cp[1] = make_float4(out[4], out[5], out[6], out[7]);
    }
}

// ---------------------------------------------------------------------------
extern "C" void kernel_launch(void* const* d_in, const int* in_sizes, int n_in,
                              void* d_out, int out_size) {
    const float* A = (const float*)d_in[0];
    float* out = (float*)d_out;

    float *S, *M, *T;
    cudaGetSymbolAddress((void**)&S, g_S);
    cudaGetSymbolAddress((void**)&M, g_M);
    cudaGetSymbolAddress((void**)&T, g_T);

    const float inv_scale = 1.0f / (float)(1 << SEXP);

    // 1) S = (A - A^T) / 2^SEXP
    {
        dim3 blk(32, 8);
        dim3 grd(MATN / 32, MATN / 32);
        skew_kernel<<<grd, blk>>>(A, S, inv_scale);
    }

    // 2) M = I + S/DEG
    {
        int threads = 256;
        int blocks = (MATN * MATN) / threads;
        init_horner_kernel<<<blocks, threads>>>(S, M, 1.0f / (float)DEG);
    }

    dim3 gblk(256);
    dim3 ggrd(MATN / 128, MATN / 128);

    // 3) Horner: M = I + (S/k) * M, k = DEG-1 .. 1
    for (int k = DEG - 1; k >= 1; k--) {
        sgemm128<true><<<ggrd, gblk>>>(S, M, T, 1.0f / (float)k);
        float* tmp = M; M = T; T = tmp;
    }

    // 4) SEXP squarings; last one writes to d_out
    for (int s = 0; s < SEXP - 1; s++) {
        sgemm128<false><<<ggrd, gblk>>>(M, M, T, 1.0f);
        float* tmp = M; M = T; T = tmp;
    }
    sgemm128<false><<<ggrd, gblk>>>(M, M, out, 1.0f);
}

// round 5
// speedup vs baseline: 5.1803x; 5.1803x over previous
#include <cuda_runtime.h>
#include <cuda_fp16.h>
#include <cstdint>

// expm(A - A^T), N=2048, degree-12 Taylor + Paterson-Stockmeyer (5 GEMMs,
// no squaring; ||S|| ~ 1.28 so truncation ~5e-9).
//   S2=S*S, S3=S*S2, S4=S2*S2
//   B3' = S + S2/10 + S3/110 + S4/1320          (=B3/c9)
//   T1' = B3'*S4
//   U'  = S + S2/6 + S3/42 + S4/336 + T1'/3024  (=U/c5)
//   B1  = I + S + S2/2 + S3/6 + S4/24
//   out = B1 + (1/120)*(U'*S4)
// GEMMs on tensor cores via mma.sync.m16n8k16 (baseline PTX, works on sm_103
// without the 'a' target) with fp16 hi/lo split (x~hi+lo, scaled by 64):
//   C = hh + hl + lh passes into one fp32 accumulator; alpha /= 4096.
// B-operands (S2,S4,S) are symmetric/antisymmetric => B^T = +-B, sign folded
// into alpha, so all operands are plain row-major fp16.

#define MATN 2048
constexpr int BM = 128, BN = 128, BK = 32, STAGES = 4;
constexpr int SKH = 40;                    // padded halves per tile row (80B)
constexpr int TILEH = 128 * SKH;           // 5120 halves per tile
constexpr int STAGEH = 4 * TILEH;          // Ah,Al,Bh,Bl
constexpr uint32_t SMEM_BYTES = STAGES * STAGEH * 2;  // 163840

// ---------------- device scratch ----------------
__device__ float g_Sf[MATN * MATN], g_S2f[MATN * MATN], g_S3f[MATN * MATN];
__device__ float g_S4f[MATN * MATN], g_T1f[MATN * MATN], g_B1f[MATN * MATN];
__device__ __half g_Sh[MATN * MATN], g_Sl[MATN * MATN];
__device__ __half g_S2h[MATN * MATN], g_S2l[MATN * MATN];
__device__ __half g_S4h[MATN * MATN], g_S4l[MATN * MATN];
__device__ __half g_B3h[MATN * MATN], g_B3l[MATN * MATN];
__device__ __half g_Uh[MATN * MATN], g_Ul[MATN * MATN];

// ---------------- PTX helpers ----------------
__device__ __forceinline__ uint32_t smem_u32(const void* p) {
    uint32_t a;
    asm("{ .reg .u64 t; cvta.to.shared.u64 t, %1; cvt.u32.u64 %0, t; }"
        : "=r"(a) : "l"(p));
    return a;
}

__device__ __forceinline__ void cp16(uint32_t dst, const void* src) {
    asm volatile("cp.async.cg.shared.global [%0], [%1], 16;"
                 :: "r"(dst), "l"(src));
}
#define CP_COMMIT() asm volatile("cp.async.commit_group;")

__device__ __forceinline__ void ldsm4(uint32_t& r0, uint32_t& r1, uint32_t& r2,
                                      uint32_t& r3, uint32_t addr) {
    asm volatile("ldmatrix.sync.aligned.m8n8.x4.shared.b16 {%0,%1,%2,%3}, [%4];"
                 : "=r"(r0), "=r"(r1), "=r"(r2), "=r"(r3) : "r"(addr));
}

__device__ __forceinline__ void mma16816(float* d, const uint32_t* a,
                                         uint32_t b0, uint32_t b1) {
    asm volatile(
        "mma.sync.aligned.m16n8k16.row.col.f32.f16.f16.f32 "
        "{%0,%1,%2,%3}, {%4,%5,%6,%7}, {%8,%9}, {%0,%1,%2,%3};"
        : "+f"(d[0]), "+f"(d[1]), "+f"(d[2]), "+f"(d[3])
        : "r"(a[0]), "r"(a[1]), "r"(a[2]), "r"(a[3]), "r"(b0), "r"(b1));
}

// ---------------------------------------------------------------------------
// GEMM: C = alpha * (Ah+Al)*(Bh+Bl)^T  [+ addC], all operands row-major fp16.
// ---------------------------------------------------------------------------
template <bool ADD_C>
__global__ __launch_bounds__(256)
void gemm_hmma(const __half* __restrict__ Ah, const __half* __restrict__ Al,
               const __half* __restrict__ Bh, const __half* __restrict__ Bl,
               float* __restrict__ C, const float* __restrict__ addC,
               float alpha) {
    extern __shared__ __half sm[];
    const uint32_t smb = smem_u32(sm);
    const int tid = threadIdx.x;
    const int lane = tid & 31, warp = tid >> 5;
    const int wm = warp >> 2, wn = warp & 3;          // 2 x 4 warps
    const int brow = blockIdx.y * BM, bcol = blockIdx.x * BN;

    const __half* srcs[4] = {Ah, Al, Bh, Bl};
    const int rbase[4] = {brow, brow, bcol, bcol};

    auto issue = [&](int chunk, int stage) {
        const int k0 = chunk * BK;
        #pragma unroll
        for (int t = 0; t < 4; t++) {
            const __half* src = srcs[t];
            const int rb = rbase[t];
            const uint32_t toff = (uint32_t)(stage * STAGEH + t * TILEH);
            #pragma unroll
            for (int i = 0; i < 2; i++) {
                int seg = tid + i * 256;          // 0..511
                int r = seg >> 2, kc = seg & 3;
                uint32_t dst = smb + (toff + r * SKH + kc * 8) * 2;
                cp16(dst, src + (size_t)(rb + r) * MATN + k0 + kc * 8);
            }
        }
        CP_COMMIT();
    };

    float acc[4][4][4];
    #pragma unroll
    for (int i = 0; i < 4; i++)
        #pragma unroll
        for (int j = 0; j < 4; j++)
            #pragma unroll
            for (int q = 0; q < 4; q++) acc[i][j][q] = 0.0f;

    issue(0, 0); issue(1, 1); issue(2, 2);

    const int NCHUNK = MATN / BK;   // 64
    // frag addresses (constant per thread, offsets vary)
    const int a_r = wm * 64 + (lane & 15);
    const int a_c = ((lane >> 4) << 3);
    const int b_r = wn * 32 + (lane & 7) + ((lane >> 4) << 3);
    const int b_c = (((lane >> 3) & 1) << 3);

    for (int k = 0; k < NCHUNK; k++) {
        if (k <= 61)      asm volatile("cp.async.wait_group 2;");
        else if (k == 62) asm volatile("cp.async.wait_group 1;");
        else              asm volatile("cp.async.wait_group 0;");
        __syncthreads();
        if (k <= 60) issue(k + 3, (k + 3) & 3);

        const uint32_t sbase = smb + ((k & 3) * STAGEH) * 2;
        #pragma unroll
        for (int ks = 0; ks < 2; ks++) {
            uint32_t ah[4][4], al[4][4], bh[2][4], bl[2][4];
            #pragma unroll
            for (int mi = 0; mi < 4; mi++) {
                uint32_t ad = sbase + ((a_r + mi * 16) * SKH + ks * 16 + a_c) * 2;
                ldsm4(ah[mi][0], ah[mi][1], ah[mi][2], ah[mi][3], ad);
                ldsm4(al[mi][0], al[mi][1], al[mi][2], al[mi][3], ad + TILEH * 2);
            }
            #pragma unroll
            for (int nj = 0; nj < 2; nj++) {
                uint32_t bd = sbase + (2 * TILEH + (b_r + nj * 16) * SKH +
                                       ks * 16 + b_c) * 2;
                ldsm4(bh[nj][0], bh[nj][1], bh[nj][2], bh[nj][3], bd);
                ldsm4(bl[nj][0], bl[nj][1], bl[nj][2], bl[nj][3], bd + TILEH * 2);
            }
            #pragma unroll
            for (int mi = 0; mi < 4; mi++)
                #pragma unroll
                for (int nj = 0; nj < 2; nj++)
                    #pragma unroll
                    for (int h = 0; h < 2; h++) {
                        float* d = acc[mi][nj * 2 + h];
                        mma16816(d, ah[mi], bh[nj][2 * h], bh[nj][2 * h + 1]);
                        mma16816(d, ah[mi], bl[nj][2 * h], bl[nj][2 * h + 1]);
                        mma16816(d, al[mi], bh[nj][2 * h], bh[nj][2 * h + 1]);
                    }
        }
    }

    // epilogue
    #pragma unroll
    for (int mi = 0; mi < 4; mi++) {
        #pragma unroll
        for (int nt = 0; nt < 4; nt++) {
            int r0 = brow + wm * 64 + mi * 16 + (lane >> 2);
            int c0 = bcol + wn * 32 + nt * 8 + 2 * (lane & 3);
            const float* d = acc[mi][nt];
            float2 v0 = {alpha * d[0], alpha * d[1]};
            float2 v1 = {alpha * d[2], alpha * d[3]};
            if (ADD_C) {
                const float2* p0 = (const float2*)(addC + (size_t)r0 * MATN + c0);
                const float2* p1 = (const float2*)(addC + (size_t)(r0 + 8) * MATN + c0);
                float2 a0 = *p0, a1 = *p1;
                v0.x += a0.x; v0.y += a0.y; v1.x += a1.x; v1.y += a1.y;
            }
            *(float2*)(C + (size_t)r0 * MATN + c0) = v0;
            *(float2*)(C + (size_t)(r0 + 8) * MATN + c0) = v1;
        }
    }
}

// ---------------------------------------------------------------------------
// elementwise kernels
// ---------------------------------------------------------------------------
__device__ __forceinline__ void split_store4(__half* H, __half* L, size_t off,
                                             const float* v) {
    __half h[4], l[4];
    #pragma unroll
    for (int j = 0; j < 4; j++) {
        float s = v[j] * 64.0f;
        h[j] = __float2half_rn(s);
        l[j] = __float2half_rn(s - __half2float(h[j]));
    }
    union { __half2 p[2]; uint2 u; } ph, pl;
    ph.p[0] = __halves2half2(h[0], h[1]); ph.p[1] = __halves2half2(h[2], h[3]);
    pl.p[0] = __halves2half2(l[0], l[1]); pl.p[1] = __halves2half2(l[2], l[3]);
    *(uint2*)(H + off) = ph.u;
    *(uint2*)(L + off) = pl.u;
}

__global__ __launch_bounds__(256)
void skew_split(const float* __restrict__ A, float* __restrict__ Sf,
                __half* __restrict__ Sh, __half* __restrict__ Sl) {
    __shared__ float t[64][65];
    int tid = threadIdx.x;
    int r0 = blockIdx.y * 64, c0 = blockIdx.x * 64;
    int tr = tid >> 4, tc = (tid & 15) * 4;
    #pragma unroll
    for (int p = 0; p < 4; p++) {
        int rr = tr + p * 16;
        float4 v = *(const float4*)(A + (size_t)(c0 + rr) * MATN + r0 + tc);
        t[rr][tc] = v.x; t[rr][tc+1] = v.y; t[rr][tc+2] = v.z; t[rr][tc+3] = v.w;
    }
    __syncthreads();
    #pragma unroll
    for (int p = 0; p < 4; p++) {
        int rr = tr + p * 16;
        int gr = r0 + rr;
        float4 a = *(const float4*)(A + (size_t)gr * MATN + c0 + tc);
        float av[4] = {a.x, a.y, a.z, a.w}, s[4];
        #pragma unroll
        for (int j = 0; j < 4; j++) s[j] = av[j] - t[tc + j][rr];
        size_t off = (size_t)gr * MATN + c0 + tc;
        *(float4*)(Sf + off) = make_float4(s[0], s[1], s[2], s[3]);
        split_store4(Sh, Sl, off, s);
    }
}

__global__ __launch_bounds__(256)
void split_mat(const float* __restrict__ X, __half* __restrict__ H,
               __half* __restrict__ L) {
    size_t base = ((size_t)blockIdx.x * 256 + threadIdx.x) * 4;
    float4 v = *(const float4*)(X + base);
    float s[4] = {v.x, v.y, v.z, v.w};
    split_store4(H, L, base, s);
}

__global__ __launch_bounds__(256)
void combo_b3(const float* __restrict__ S, const float* __restrict__ S2,
              const float* __restrict__ S3, const float* __restrict__ S4,
              __half* __restrict__ H, __half* __restrict__ L) {
    size_t base = ((size_t)blockIdx.x * 256 + threadIdx.x) * 4;
    float4 a = *(const float4*)(S + base);
    float4 b = *(const float4*)(S2 + base);
    float4 c = *(const float4*)(S3 + base);
    float4 d = *(const float4*)(S4 + base);
    const float r2 = 1.0f/10.0f, r3 = 1.0f/110.0f, r4 = 1.0f/1320.0f;
    float v[4] = {a.x + r2*b.x + r3*c.x + r4*d.x,
                  a.y + r2*b.y + r3*c.y + r4*d.y,
                  a.z + r2*b.z + r3*c.z + r4*d.z,
                  a.w + r2*b.w + r3*c.w + r4*d.w};
    split_store4(H, L, base, v);
}

__global__ __launch_bounds__(256)
void combo_u(const float* __restrict__ S, const float* __restrict__ S2,
             const float* __restrict__ S3, const float* __restrict__ S4,
             const float* __restrict__ T1, __half* __restrict__ UH,
             __half* __restrict__ UL, float* __restrict__ B1) {
    size_t base = ((size_t)blockIdx.x * 256 + threadIdx.x) * 4;
    float4 a = *(const float4*)(S + base);
    float4 b = *(const float4*)(S2 + base);
    float4 c = *(const float4*)(S3 + base);
    float4 d = *(const float4*)(S4 + base);
    float4 t = *(const float4*)(T1 + base);
    const float u2 = 1.0f/6.0f, u3 = 1.0f/42.0f, u4 = 1.0f/336.0f, ut = 1.0f/3024.0f;
    float u[4] = {a.x + u2*b.x + u3*c.x + u4*d.x + ut*t.x,
                  a.y + u2*b.y + u3*c.y + u4*d.y + ut*t.y,
                  a.z + u2*b.z + u3*c.z + u4*d.z + ut*t.z,
                  a.w + u2*b.w + u3*c.w + u4*d.w + ut*t.w};
    split_store4(UH, UL, base, u);
    const float b2 = 0.5f, b3 = 1.0f/6.0f, b4 = 1.0f/24.0f;
    int row = (int)(base >> 11), col = (int)(base & 2047);
    float e[4];
    #pragma unroll
    for (int j = 0; j < 4; j++) {
        float diag = (row == col + j) ? 1.0f : 0.0f;
        float sv = (&a.x)[j], s2v = (&b.x)[j], s3v = (&c.x)[j], s4v = (&d.x)[j];
        e[j] = diag + sv + b2*s2v + b3*s3v + b4*s4v;
    }
    *(float4*)(B1 + base) = make_float4(e[0], e[1], e[2], e[3]);
}

// ---------------------------------------------------------------------------
extern "C" void kernel_launch(void* const* d_in, const int* in_sizes, int n_in,
                              void* d_out, int out_size) {
    const float* A = (const float*)d_in[0];
    float* out = (float*)d_out;

    float *Sf, *S2f, *S3f, *S4f, *T1f, *B1f;
    __half *Sh, *Sl, *S2h, *S2l, *S4h, *S4l, *B3h, *B3l, *Uh, *Ul;
    cudaGetSymbolAddress((void**)&Sf, g_Sf);
    cudaGetSymbolAddress((void**)&S2f, g_S2f);
    cudaGetSymbolAddress((void**)&S3f, g_S3f);
    cudaGetSymbolAddress((void**)&S4f, g_S4f);
    cudaGetSymbolAddress((void**)&T1f, g_T1f);
    cudaGetSymbolAddress((void**)&B1f, g_B1f);
    cudaGetSymbolAddress((void**)&Sh, g_Sh);
    cudaGetSymbolAddress((void**)&Sl, g_Sl);
    cudaGetSymbolAddress((void**)&S2h, g_S2h);
    cudaGetSymbolAddress((void**)&S2l, g_S2l);
    cudaGetSymbolAddress((void**)&S4h, g_S4h);
    cudaGetSymbolAddress((void**)&S4l, g_S4l);
    cudaGetSymbolAddress((void**)&B3h, g_B3h);
    cudaGetSymbolAddress((void**)&B3l, g_B3l);
    cudaGetSymbolAddress((void**)&Uh, g_Uh);
    cudaGetSymbolAddress((void**)&Ul, g_Ul);

    cudaFuncSetAttribute(gemm_hmma<false>,
                         cudaFuncAttributeMaxDynamicSharedMemorySize, SMEM_BYTES);
    cudaFuncSetAttribute(gemm_hmma<true>,
                         cudaFuncAttributeMaxDynamicSharedMemorySize, SMEM_BYTES);

    const float INV = 1.0f / 4096.0f;   // undo 64x split scaling
    dim3 gg(MATN / BN, MATN / BM);      // 16 x 16
    dim3 sb(32, 32);
    const int EW_BLOCKS = (MATN * MATN / 4) / 256;   // 4096

    // S = A - A^T; split
    skew_split<<<sb, 256>>>(A, Sf, Sh, Sl);
    // S2 = S*S   (mma gives S*S^T = -S2)
    gemm_hmma<false><<<gg, 256, SMEM_BYTES>>>(Sh, Sl, Sh, Sl, S2f, nullptr, -INV);
    split_mat<<<EW_BLOCKS, 256>>>(S2f, S2h, S2l);
    // S3 = S*S2  (S2 symmetric)
    gemm_hmma<false><<<gg, 256, SMEM_BYTES>>>(Sh, Sl, S2h, S2l, S3f, nullptr, INV);
    // S4 = S2*S2
    gemm_hmma<false><<<gg, 256, SMEM_BYTES>>>(S2h, S2l, S2h, S2l, S4f, nullptr, INV);
    split_mat<<<EW_BLOCKS, 256>>>(S4f, S4h, S4l);
    // B3' and T1' = B3'*S4
    combo_b3<<<EW_BLOCKS, 256>>>(Sf, S2f, S3f, S4f, B3h, B3l);
    gemm_hmma<false><<<gg, 256, SMEM_BYTES>>>(B3h, B3l, S4h, S4l, T1f, nullptr, INV);
    // U', B1
    combo_u<<<EW_BLOCKS, 256>>>(Sf, S2f, S3f, S4f, T1f, Uh, Ul, B1f);
    // out = B1 + (1/120) * U'*S4
    gemm_hmma<true><<<gg, 256, SMEM_BYTES>>>(Uh, Ul, S4h, S4l, out, B1f,
                                             INV / 120.0f);
}

// round 7
// speedup vs baseline: 9.2685x; 1.7892x over previous
#include <cuda_runtime.h>
#include <cuda_fp16.h>
#include <cstdint>

// expm(A - A^T), N=2048, degree-12 Taylor + Paterson-Stockmeyer, 5 HMMA GEMMs.
//   S2=S*S (sym), S3=S*S2 (antisym), S4=S2*S2 (sym)
//   B3' = S + S2/10 + S3/110 + S4/1320
//   U'  = S + S2/6 + S3/42 + S4/336 + (B3'*S4)/3024
//   B1  = I + S + S2/2 + S3/6 + S4/24
//   out = B1 + (1/120)*(U'*S4)
// fp16 hi/lo split (x64 scale), mma.sync.m16n8k16.
//   G1 (S2): 3 passes (hh+hl+lh), symmetric -> triangular grid + mirror.
//   G2,G3:   2 passes ((Ah+Al)*Bh), (anti)symmetric -> triangular + mirror.
//   G4,G5:   2 passes, full grid.
// Elementwise combos fused into GEMM epilogues (T1 never materialized).

#define MATN 2048
constexpr int BK = 32, STAGES = 3;
constexpr int SKH = 40;                 // padded halves per tile row
constexpr int TILEH = 128 * SKH;        // 5120 halves = 10240 B per tile

// ---------------- device scratch ----------------
__device__ float g_Sf[MATN * MATN], g_S2f[MATN * MATN], g_S3f[MATN * MATN];
__device__ float g_S4f[MATN * MATN], g_B1f[MATN * MATN];
__device__ __half g_Sh[MATN * MATN], g_Sl[MATN * MATN];
__device__ __half g_S2h[MATN * MATN], g_S2l[MATN * MATN];
__device__ __half g_S4h[MATN * MATN], g_S4l[MATN * MATN];
__device__ __half g_B3h[MATN * MATN], g_B3l[MATN * MATN];
__device__ __half g_Uh[MATN * MATN], g_Ul[MATN * MATN];

// ---------------- PTX helpers ----------------
__device__ __forceinline__ uint32_t smem_u32(const void* p) {
    uint32_t a;
    asm("{ .reg .u64 t; cvta.to.shared.u64 t, %1; cvt.u32.u64 %0, t; }"
        : "=r"(a) : "l"(p));
    return a;
}
__device__ __forceinline__ void cp16(uint32_t dst, const void* src) {
    asm volatile("cp.async.cg.shared.global [%0], [%1], 16;"
                 :: "r"(dst), "l"(src));
}
#define CP_COMMIT() asm volatile("cp.async.commit_group;")

__device__ __forceinline__ void ldsm4(uint32_t& r0, uint32_t& r1, uint32_t& r2,
                                      uint32_t& r3, uint32_t addr) {
    asm volatile("ldmatrix.sync.aligned.m8n8.x4.shared.b16 {%0,%1,%2,%3}, [%4];"
                 : "=r"(r0), "=r"(r1), "=r"(r2), "=r"(r3) : "r"(addr));
}
__device__ __forceinline__ void mma16816(float* d, const uint32_t* a,
                                         uint32_t b0, uint32_t b1) {
    asm volatile(
        "mma.sync.aligned.m16n8k16.row.col.f32.f16.f16.f32 "
        "{%0,%1,%2,%3}, {%4,%5,%6,%7}, {%8,%9}, {%0,%1,%2,%3};"
        : "+f"(d[0]), "+f"(d[1]), "+f"(d[2]), "+f"(d[3])
        : "r"(a[0]), "r"(a[1]), "r"(a[2]), "r"(a[3]), "r"(b0), "r"(b1));
}

__device__ __forceinline__ void split2(float2 v, __half2& h2, __half2& l2) {
    float sx = v.x * 64.0f, sy = v.y * 64.0f;
    __half hx = __float2half_rn(sx), hy = __float2half_rn(sy);
    __half lx = __float2half_rn(sx - __half2float(hx));
    __half ly = __float2half_rn(sy - __half2float(hy));
    h2 = __halves2half2(hx, hy);
    l2 = __halves2half2(lx, ly);
}

// ---------------------------------------------------------------------------
// GEMM: acc = A*B^T with A=(Ah[+Al]) fp16-split, B=Bh (+Bl if PASSES==3).
// MODE epilogues: 0=plain Cf; 1=Cf+split(Ch,Cl); 2=S4(+split)+B3 combo;
//                 3=U split + B1; 4=out = X1 + alpha*acc.
// SYM: 0 full grid; +1/-1 triangular grid with (anti)symmetric mirror writes.
// ---------------------------------------------------------------------------
template <int PASSES, int MODE, int SYM>
__global__ __launch_bounds__(256, 2)
void gemm_hmma(const __half* __restrict__ Ah, const __half* __restrict__ Al,
               const __half* __restrict__ Bh, const __half* __restrict__ Bl,
               float* __restrict__ Cf, __half* __restrict__ Ch,
               __half* __restrict__ Cl, __half* __restrict__ Dh,
               __half* __restrict__ Dl,
               const float* __restrict__ X1, const float* __restrict__ X2,
               const float* __restrict__ X3, const float* __restrict__ X4,
               float alpha) {
    constexpr int NTILES = (PASSES == 3) ? 4 : 3;
    constexpr int STAGEH = NTILES * TILEH;
    extern __shared__ __half sm[];
    const uint32_t smb = smem_u32(sm);
    const int tid = threadIdx.x;
    const int lane = tid & 31, warp = tid >> 5;
    const int wm = warp >> 2, wn = warp & 3;          // 2 x 4 warps

    int bi, bj;
    if (SYM != 0) {
        int idx = blockIdx.x;
        bi = 0;
        int rem = 16;
        while (idx >= rem) { idx -= rem; bi++; rem = 16 - bi; }
        bj = bi + idx;
    } else {
        bi = blockIdx.y; bj = blockIdx.x;
    }
    const int brow = bi * 128, bcol = bj * 128;
    const bool mir = (SYM != 0) && (bj > bi);

    const __half* srcs[4] = {Ah, Al, Bh, Bl};
    const int rbase[4] = {brow, brow, bcol, bcol};

    auto issue = [&](int chunk, int stage) {
        const int k0 = chunk * BK;
        #pragma unroll
        for (int t = 0; t < NTILES; t++) {
            const __half* src = srcs[t];
            const int rb = rbase[t];
            const uint32_t toff = (uint32_t)(stage * STAGEH + t * TILEH);
            #pragma unroll
            for (int i = 0; i < 2; i++) {
                int seg = tid + i * 256;
                int r = seg >> 2, kc = seg & 3;
                uint32_t dst = smb + (toff + r * SKH + kc * 8) * 2;
                cp16(dst, src + (size_t)(rb + r) * MATN + k0 + kc * 8);
            }
        }
        CP_COMMIT();
    };

    float acc[4][4][4];
    #pragma unroll
    for (int i = 0; i < 4; i++)
        #pragma unroll
        for (int j = 0; j < 4; j++)
            #pragma unroll
            for (int q = 0; q < 4; q++) acc[i][j][q] = 0.0f;

    issue(0, 0); issue(1, 1);

    const int NCHUNK = MATN / BK;   // 64
    const int a_r = wm * 64 + (lane & 15);
    const int a_c = ((lane >> 4) << 3);
    const int b_r = wn * 32 + (lane & 7) + ((lane >> 4) << 3);
    const int b_c = (((lane >> 3) & 1) << 3);

    int stage = 0;
    for (int k = 0; k < NCHUNK; k++) {
        if (k <= NCHUNK - 3) asm volatile("cp.async.wait_group 1;");
        else                 asm volatile("cp.async.wait_group 0;");
        __syncthreads();
        if (k <= NCHUNK - 3) {
            int ns = stage + 2; if (ns >= 3) ns -= 3;
            issue(k + 2, ns);
        }

        const uint32_t sbase = smb + (stage * STAGEH) * 2;
        #pragma unroll
        for (int ks = 0; ks < 2; ks++) {
            uint32_t ah[4][4], al[4][4], bh[2][4], bl[2][4];
            #pragma unroll
            for (int mi = 0; mi < 4; mi++) {
                uint32_t ad = sbase + ((a_r + mi * 16) * SKH + ks * 16 + a_c) * 2;
                ldsm4(ah[mi][0], ah[mi][1], ah[mi][2], ah[mi][3], ad);
                ldsm4(al[mi][0], al[mi][1], al[mi][2], al[mi][3], ad + TILEH * 2);
            }
            #pragma unroll
            for (int nj = 0; nj < 2; nj++) {
                uint32_t bd = sbase + (2 * TILEH + (b_r + nj * 16) * SKH +
                                       ks * 16 + b_c) * 2;
                ldsm4(bh[nj][0], bh[nj][1], bh[nj][2], bh[nj][3], bd);
                if (PASSES == 3)
                    ldsm4(bl[nj][0], bl[nj][1], bl[nj][2], bl[nj][3],
                          bd + TILEH * 2);
            }
            #pragma unroll
            for (int mi = 0; mi < 4; mi++)
                #pragma unroll
                for (int nj = 0; nj < 2; nj++)
                    #pragma unroll
                    for (int h = 0; h < 2; h++) {
                        float* d = acc[mi][nj * 2 + h];
                        mma16816(d, ah[mi], bh[nj][2 * h], bh[nj][2 * h + 1]);
                        mma16816(d, al[mi], bh[nj][2 * h], bh[nj][2 * h + 1]);
                        if (PASSES == 3)
                            mma16816(d, ah[mi], bl[nj][2 * h], bl[nj][2 * h + 1]);
                    }
        }
        stage++; if (stage >= 3) stage = 0;
    }

    // -------- fused epilogue --------
    auto do_row = [&](int rr, int cc, float dx, float dy) {
        float2 v = {alpha * dx, alpha * dy};
        size_t off = (size_t)rr * MATN + cc;
        size_t m0 = (size_t)cc * MATN + rr, m1 = (size_t)(cc + 1) * MATN + rr;
        if (MODE == 0) {
            *(float2*)(Cf + off) = v;
            if (SYM == -1 && mir) { Cf[m0] = -v.x; Cf[m1] = -v.y; }
        } else if (MODE == 1) {
            *(float2*)(Cf + off) = v;
            __half2 h2, l2; split2(v, h2, l2);
            *(__half2*)(Ch + off) = h2;
            *(__half2*)(Cl + off) = l2;
            if (SYM == 1 && mir) {
                Cf[m0] = v.x; Cf[m1] = v.y;
                Ch[m0] = __low2half(h2); Ch[m1] = __high2half(h2);
                Cl[m0] = __low2half(l2); Cl[m1] = __high2half(l2);
            }
        } else if (MODE == 2) {
            // acc = S4; X1=S, X2=S2, X3=S3
            float2 s = *(const float2*)(X1 + off);
            float2 s2 = *(const float2*)(X2 + off);
            float2 s3 = *(const float2*)(X3 + off);
            *(float2*)(Cf + off) = v;
            __half2 h2, l2; split2(v, h2, l2);
            *(__half2*)(Ch + off) = h2;
            *(__half2*)(Cl + off) = l2;
            const float r2 = 0.1f, r3 = 1.0f / 110.0f, r4 = 1.0f / 1320.0f;
            float2 b3 = {s.x + r2 * s2.x + r3 * s3.x + r4 * v.x,
                         s.y + r2 * s2.y + r3 * s3.y + r4 * v.y};
            __half2 bh2, bl2; split2(b3, bh2, bl2);
            *(__half2*)(Dh + off) = bh2;
            *(__half2*)(Dl + off) = bl2;
            if (mir) {
                Cf[m0] = v.x; Cf[m1] = v.y;
                Ch[m0] = __low2half(h2); Ch[m1] = __high2half(h2);
                Cl[m0] = __low2half(l2); Cl[m1] = __high2half(l2);
                // B3(c,r): S,S3 antisym; S2,S4 sym
                float2 b3m = {-s.x + r2 * s2.x - r3 * s3.x + r4 * v.x,
                              -s.y + r2 * s2.y - r3 * s3.y + r4 * v.y};
                __half2 mh2, ml2; split2(b3m, mh2, ml2);
                Dh[m0] = __low2half(mh2); Dh[m1] = __high2half(mh2);
                Dl[m0] = __low2half(ml2); Dl[m1] = __high2half(ml2);
            }
        } else if (MODE == 3) {
            // acc = T1'; X1=S, X2=S2, X3=S3, X4=S4; Ch/Cl=U split, Cf=B1
            float2 s = *(const float2*)(X1 + off);
            float2 s2 = *(const float2*)(X2 + off);
            float2 s3 = *(const float2*)(X3 + off);
            float2 s4 = *(const float2*)(X4 + off);
            const float u2 = 1.0f / 6.0f, u3 = 1.0f / 42.0f;
            const float u4 = 1.0f / 336.0f, ut = 1.0f / 3024.0f;
            float2 u = {s.x + u2 * s2.x + u3 * s3.x + u4 * s4.x + ut * v.x,
                        s.y + u2 * s2.y + u3 * s3.y + u4 * s4.y + ut * v.y};
            __half2 h2, l2; split2(u, h2, l2);
            *(__half2*)(Ch + off) = h2;
            *(__half2*)(Cl + off) = l2;
            const float b2 = 0.5f, b3c = 1.0f / 6.0f, b4 = 1.0f / 24.0f;
            float2 b1 = {(rr == cc ? 1.0f : 0.0f) + s.x + b2 * s2.x +
                             b3c * s3.x + b4 * s4.x,
                         (rr == cc + 1 ? 1.0f : 0.0f) + s.y + b2 * s2.y +
                             b3c * s3.y + b4 * s4.y};
            *(float2*)(Cf + off) = b1;
        } else {  // MODE 4: out = X1 + alpha*acc
            float2 b = *(const float2*)(X1 + off);
            float2 o = {b.x + v.x, b.y + v.y};
            *(float2*)(Cf + off) = o;
        }
    };

    #pragma unroll
    for (int mi = 0; mi < 4; mi++) {
        #pragma unroll
        for (int nt = 0; nt < 4; nt++) {
            int r0 = brow + wm * 64 + mi * 16 + (lane >> 2);
            int c0 = bcol + wn * 32 + nt * 8 + 2 * (lane & 3);
            const float* d = acc[mi][nt];
            do_row(r0, c0, d[0], d[1]);
            do_row(r0 + 8, c0, d[2], d[3]);
        }
    }
}

// ---------------------------------------------------------------------------
__global__ __launch_bounds__(256)
void skew_split(const float* __restrict__ A, float* __restrict__ Sf,
                __half* __restrict__ Sh, __half* __restrict__ Sl) {
    __shared__ float t[64][65];
    int tid = threadIdx.x;
    int r0 = blockIdx.y * 64, c0 = blockIdx.x * 64;
    int tr = tid >> 4, tc = (tid & 15) * 4;
    #pragma unroll
    for (int p = 0; p < 4; p++) {
        int rr = tr + p * 16;
        float4 v = *(const float4*)(A + (size_t)(c0 + rr) * MATN + r0 + tc);
        t[rr][tc] = v.x; t[rr][tc+1] = v.y; t[rr][tc+2] = v.z; t[rr][tc+3] = v.w;
    }
    __syncthreads();
    #pragma unroll
    for (int p = 0; p < 4; p++) {
        int rr = tr + p * 16;
        int gr = r0 + rr;
        float4 a = *(const float4*)(A + (size_t)gr * MATN + c0 + tc);
        float av[4] = {a.x, a.y, a.z, a.w}, s[4];
        #pragma unroll
        for (int j = 0; j < 4; j++) s[j] = av[j] - t[tc + j][rr];
        size_t off = (size_t)gr * MATN + c0 + tc;
        *(float4*)(Sf + off) = make_float4(s[0], s[1], s[2], s[3]);
        float2 v0 = {s[0], s[1]}, v1 = {s[2], s[3]};
        __half2 h0, l0, h1, l1;
        split2(v0, h0, l0); split2(v1, h1, l1);
        *(__half2*)(Sh + off) = h0; *(__half2*)(Sh + off + 2) = h1;
        *(__half2*)(Sl + off) = l0; *(__half2*)(Sl + off + 2) = l1;
    }
}

// ---------------------------------------------------------------------------
extern "C" void kernel_launch(void* const* d_in, const int* in_sizes, int n_in,
                              void* d_out, int out_size) {
    const float* A = (const float*)d_in[0];
    float* out = (float*)d_out;

    float *Sf, *S2f, *S3f, *S4f, *B1f;
    __half *Sh, *Sl, *S2h, *S2l, *S4h, *S4l, *B3h, *B3l, *Uh, *Ul;
    cudaGetSymbolAddress((void**)&Sf, g_Sf);
    cudaGetSymbolAddress((void**)&S2f, g_S2f);
    cudaGetSymbolAddress((void**)&S3f, g_S3f);
    cudaGetSymbolAddress((void**)&S4f, g_S4f);
    cudaGetSymbolAddress((void**)&B1f, g_B1f);
    cudaGetSymbolAddress((void**)&Sh, g_Sh);
    cudaGetSymbolAddress((void**)&Sl, g_Sl);
    cudaGetSymbolAddress((void**)&S2h, g_S2h);
    cudaGetSymbolAddress((void**)&S2l, g_S2l);
    cudaGetSymbolAddress((void**)&S4h, g_S4h);
    cudaGetSymbolAddress((void**)&S4l, g_S4l);
    cudaGetSymbolAddress((void**)&B3h, g_B3h);
    cudaGetSymbolAddress((void**)&B3l, g_B3l);
    cudaGetSymbolAddress((void**)&Uh, g_Uh);
    cudaGetSymbolAddress((void**)&Ul, g_Ul);

    constexpr uint32_t SM3P = STAGES * 4 * TILEH * 2;  // 122880
    constexpr uint32_t SM2P = STAGES * 3 * TILEH * 2;  // 92160
    cudaFuncSetAttribute(gemm_hmma<3, 1, 1>,
                         cudaFuncAttributeMaxDynamicSharedMemorySize, SM3P);
    cudaFuncSetAttribute(gemm_hmma<2, 0, -1>,
                         cudaFuncAttributeMaxDynamicSharedMemorySize, SM2P);
    cudaFuncSetAttribute(gemm_hmma<2, 2, 1>,
                         cudaFuncAttributeMaxDynamicSharedMemorySize, SM2P);
    cudaFuncSetAttribute(gemm_hmma<2, 3, 0>,
                         cudaFuncAttributeMaxDynamicSharedMemorySize, SM2P);
    cudaFuncSetAttribute(gemm_hmma<2, 4, 0>,
                         cudaFuncAttributeMaxDynamicSharedMemorySize, SM2P);

    const float INV = 1.0f / 4096.0f;
    dim3 full(16, 16);

    // S = A - A^T (+ split)
    skew_split<<<dim3(32, 32), 256>>>(A, Sf, Sh, Sl);
    // G1: S2 = -(S*S^T), sym, 3-pass, fused split
    gemm_hmma<3, 1, 1><<<136, 256, SM3P>>>(
        Sh, Sl, Sh, Sl, S2f, S2h, S2l, nullptr, nullptr,
        nullptr, nullptr, nullptr, nullptr, -INV);
    // G2: S3 = S*S2, antisym, 2-pass
    gemm_hmma<2, 0, -1><<<136, 256, SM2P>>>(
        Sh, Sl, S2h, nullptr, S3f, nullptr, nullptr, nullptr, nullptr,
        nullptr, nullptr, nullptr, nullptr, INV);
    // G3: S4 = S2*S2, sym, 2-pass, fused split + B3 combo
    gemm_hmma<2, 2, 1><<<136, 256, SM2P>>>(
        S2h, S2l, S2h, nullptr, S4f, S4h, S4l, B3h, B3l,
        Sf, S2f, S3f, nullptr, INV);
    // G4: T1' = B3'*S4 -> fused U split + B1
    gemm_hmma<2, 3, 0><<<full, 256, SM2P>>>(
        B3h, B3l, S4h, nullptr, B1f, Uh, Ul, nullptr, nullptr,
        Sf, S2f, S3f, S4f, INV);
    // G5: out = B1 + (1/120)*U'*S4
    gemm_hmma<2, 4, 0><<<full, 256, SM2P>>>(
        Uh, Ul, S4h, nullptr, out, nullptr, nullptr, nullptr, nullptr,
        B1f, nullptr, nullptr, nullptr, INV / 120.0f);
}